// round 7
// baseline (speedup 1.0000x reference)
#include <cuda_runtime.h>
#include <cstdint>

#define NB 64
#define NC 2048
#define NPOS9 729          // 27*27
#define TOTPOS (NB*NPOS9)  // 46656
#define KSEL 819
#define SEL_CAP 1024       // fallback list cap
#define SEG_CAP 48
#define SEG_STRIDE 49
#define LIST_CAP 128
#define T0 0x40000000u
#define RNG 0x10000000u

__device__ float g_conv[(size_t)NB * NPOS9 * NC];  // NHWC: [b][p][c]
__device__ float g_t1[TOTPOS];
__device__ float g_t2[TOTPOS];

// ---------------------------------------------------------------------------
// Kernel 1: conv (VALID, stride 1) -> NHWC scratch.  fp32 via fma.rn.f32x2.
// ---------------------------------------------------------------------------
#define CONV_XS2_U64 3072
#define CONV_W_U64  (108 * 4 * 16)
#define CONV_SMEM ((CONV_XS2_U64 + CONV_W_U64) * 8)

__global__ void __launch_bounds__(256) conv_kernel(const float* __restrict__ x,
                                                   const float* __restrict__ w)
{
    extern __shared__ unsigned long long smem64[];
    float2* xs2 = (float2*)smem64;                       // 3072 pairs {x,x}
    float2* ws2 = (float2*)(smem64 + CONV_XS2_U64);      // 6912 weight pairs
    const unsigned long long* xsu = smem64;
    const unsigned long long* wsu = smem64 + CONV_XS2_U64;

    const int b = blockIdx.y;
    const int c0 = blockIdx.x * 128;
    const int tid = threadIdx.x;

    {
        const float* xsrc = x + (size_t)b * 3072;
        #pragma unroll
        for (int i = 0; i < 12; i++) {
            int idx = tid + 256 * i;
            float v = xsrc[idx];
            xs2[idx] = make_float2(v, v);
        }
    }
    for (int idx = tid; idx < CONV_W_U64; idx += 256) {
        int ct = idx & 15;
        int kq = idx >> 4;
        int k = kq >> 2, q = kq & 3;
        int ch = c0 + ct * 8 + 2 * q;
        float a = w[(size_t)ch * 108 + k];
        float bb = w[(size_t)(ch + 1) * 108 + k];
        ws2[idx] = make_float2(a, bb);
    }
    __syncthreads();

    const int ch_tid = tid & 15;
    const int pos_tid = tid >> 4;
    const int ch0 = ch_tid * 8;

    for (int chunk = 0; chunk < 6; chunk++) {
        const int p0 = chunk * 128 + pos_tid * 8;
        int pbase[8];
        #pragma unroll
        for (int pp = 0; pp < 8; pp++) {
            int p = p0 + pp; if (p > 728) p = 728;
            int y = p / 27;
            pbase[pp] = y * 32 + (p - y * 27);
        }
        unsigned long long acc0[8], acc1[8], acc2[8], acc3[8];
        #pragma unroll
        for (int pp = 0; pp < 8; pp++) { acc0[pp] = 0ull; acc1[pp] = 0ull; acc2[pp] = 0ull; acc3[pp] = 0ull; }

        #pragma unroll 1
        for (int c = 0; c < 3; c++) {
            #pragma unroll 1
            for (int i = 0; i < 6; i++) {
                const unsigned long long* xrow = xsu + c * 1024 + i * 32;
                const int kbase = (c * 36 + i * 6) * 4;
                #pragma unroll
                for (int j = 0; j < 6; j++) {
                    const unsigned long long* wk = wsu + (size_t)(kbase + j * 4) * 16 + ch_tid;
                    unsigned long long w0 = wk[0], w1 = wk[16], w2 = wk[32], w3 = wk[48];
                    #pragma unroll
                    for (int pp = 0; pp < 8; pp++) {
                        unsigned long long xx = xrow[pbase[pp] + j];
                        asm("fma.rn.f32x2 %0, %1, %2, %0;" : "+l"(acc0[pp]) : "l"(w0), "l"(xx));
                        asm("fma.rn.f32x2 %0, %1, %2, %0;" : "+l"(acc1[pp]) : "l"(w1), "l"(xx));
                        asm("fma.rn.f32x2 %0, %1, %2, %0;" : "+l"(acc2[pp]) : "l"(w2), "l"(xx));
                        asm("fma.rn.f32x2 %0, %1, %2, %0;" : "+l"(acc3[pp]) : "l"(w3), "l"(xx));
                    }
                }
            }
        }
        #pragma unroll
        for (int pp = 0; pp < 8; pp++) {
            int p = p0 + pp;
            if (p < 729) {
                float* dst = g_conv + ((size_t)(b * NPOS9 + p)) * NC + c0 + ch0;
                float a, bb, cc, dd, e, f, g, h;
                asm("mov.b64 {%0, %1}, %2;" : "=f"(a), "=f"(bb) : "l"(acc0[pp]));
                asm("mov.b64 {%0, %1}, %2;" : "=f"(cc), "=f"(dd) : "l"(acc1[pp]));
                asm("mov.b64 {%0, %1}, %2;" : "=f"(e), "=f"(f) : "l"(acc2[pp]));
                asm("mov.b64 {%0, %1}, %2;" : "=f"(g), "=f"(h) : "l"(acc3[pp]));
                ((float4*)dst)[0] = make_float4(a, bb, cc, dd);
                ((float4*)dst)[1] = make_float4(e, f, g, h);
            }
        }
    }
}

// ---------------------------------------------------------------------------
// Kernel 2: per-thread privatized select (no collectives in hot path).
// ---------------------------------------------------------------------------
__device__ __forceinline__ unsigned f2u(float f) {
    int b = __float_as_int(f);
    return (unsigned)(b ^ ((b >> 31) | 0x80000000));
}
__device__ __forceinline__ float u2f(unsigned u) {
    unsigned b = (u & 0x80000000u) ? (u & 0x7fffffffu) : ~u;
    return __uint_as_float(b);
}
__device__ __forceinline__ int wsum(int v) {
    #pragma unroll
    for (int o = 16; o; o >>= 1) v += __shfl_xor_sync(~0u, v, o);
    return v;
}

// ---- general exact fallback machinery (rare path) ----
template<bool MASKED>
__device__ __forceinline__ int hist_sweep(const float4* __restrict__ vsrc,
                                          const float* __restrict__ sbias,
                                          unsigned top1, unsigned top2,
                                          unsigned maskTop, int shift, int lane)
{
    const unsigned bin = lane & 15;
    const unsigned r0 = (bin & 1) ? ~0u : 0u;
    const unsigned r1 = (bin & 2) ? ~0u : 0u;
    const unsigned r2 = (bin & 4) ? ~0u : 0u;
    const unsigned r3 = (bin & 8) ? ~0u : 0u;
    const bool br2 = (lane >= 16);
    int cnt = 0;
    const float4* bs4 = (const float4*)sbias;
    for (int t = 0; t < 16; t++) {
        float4 v4 = __ldg(vsrc + t * 32 + lane);
        float4 b4 = bs4[t * 32 + lane];
        #pragma unroll
        for (int e = 0; e < 4; e++) {
            float v = (&v4.x)[e], bb = (&b4.x)[e];
            unsigned u1 = f2u(bb - v), u2 = f2u(bb + v);
            bool a1 = MASKED ? (((u1 ^ top1) & maskTop) == 0) : true;
            bool a2 = MASKED ? (((u2 ^ top2) & maskTop) == 0) : true;
            unsigned d1 = u1 >> shift, d2 = u2 >> shift;
            unsigned B10 = __ballot_sync(~0u, a1 && (d1 & 1));
            unsigned B11 = __ballot_sync(~0u, a1 && (d1 & 2));
            unsigned B12 = __ballot_sync(~0u, a1 && (d1 & 4));
            unsigned B13 = __ballot_sync(~0u, a1 && (d1 & 8));
            unsigned A1  = MASKED ? __ballot_sync(~0u, a1) : ~0u;
            unsigned B20 = __ballot_sync(~0u, a2 && (d2 & 1));
            unsigned B21 = __ballot_sync(~0u, a2 && (d2 & 2));
            unsigned B22 = __ballot_sync(~0u, a2 && (d2 & 4));
            unsigned B23 = __ballot_sync(~0u, a2 && (d2 & 8));
            unsigned A2  = MASKED ? __ballot_sync(~0u, a2) : ~0u;
            unsigned Bb0 = br2 ? B20 : B10;
            unsigned Bb1 = br2 ? B21 : B11;
            unsigned Bb2 = br2 ? B22 : B12;
            unsigned Bb3 = br2 ? B23 : B13;
            unsigned A   = br2 ? A2  : A1;
            unsigned mm = A & ~((Bb3 ^ r3) | (Bb2 ^ r2) | (Bb1 ^ r1) | (Bb0 ^ r0));
            cnt += __popc(mm);
        }
    }
    return cnt;
}

__device__ __forceinline__ void pick_bins(int cnt, int& rank1, int& rank2,
                                          unsigned& dig1, unsigned& dig2,
                                          int& m1, int& m2, int lane)
{
    int incl = cnt;
    #pragma unroll
    for (int o = 1; o < 16; o <<= 1) {
        int n = __shfl_up_sync(~0u, incl, o, 16);
        if ((lane & 15) >= o) incl += n;
    }
    int excl = incl - cnt;
    int rk = (lane < 16) ? rank1 : rank2;
    bool hit = (rk >= excl) && (rk < incl);
    unsigned bal = __ballot_sync(~0u, hit);
    int src1 = __ffs(bal & 0xFFFFu) - 1;
    int src2 = 31 - __clz(bal & 0xFFFF0000u);
    int nr = rk - excl;
    dig1 = (unsigned)(src1 & 15);
    dig2 = (unsigned)(src2 & 15);
    rank1 = __shfl_sync(~0u, nr, src1);
    rank2 = __shfl_sync(~0u, nr, src2);
    m1 = __shfl_sync(~0u, cnt, src1);
    m2 = __shfl_sync(~0u, cnt, src2);
}

__device__ __forceinline__ void compact_sweep(const float4* __restrict__ vsrc,
                                              const float* __restrict__ sbias,
                                              unsigned top1, unsigned top2,
                                              unsigned maskTop,
                                              unsigned* l1, unsigned* l2,
                                              bool en1, bool en2, int lane)
{
    int n1 = 0, n2 = 0;
    const unsigned lt = (1u << lane) - 1u;
    const float4* bs4 = (const float4*)sbias;
    for (int t = 0; t < 16; t++) {
        float4 v4 = __ldg(vsrc + t * 32 + lane);
        float4 b4 = bs4[t * 32 + lane];
        #pragma unroll
        for (int e = 0; e < 4; e++) {
            float v = (&v4.x)[e], bb = (&b4.x)[e];
            unsigned u1 = f2u(bb - v), u2 = f2u(bb + v);
            bool k1 = en1 && (((u1 ^ top1) & maskTop) == 0);
            bool k2 = en2 && (((u2 ^ top2) & maskTop) == 0);
            unsigned bal1 = __ballot_sync(~0u, k1);
            if (k1) l1[n1 + __popc(bal1 & lt)] = u1;
            n1 += __popc(bal1);
            unsigned bal2 = __ballot_sync(~0u, k2);
            if (k2) l2[n2 + __popc(bal2 & lt)] = u2;
            n2 += __popc(bal2);
        }
    }
}

__device__ __forceinline__ unsigned list_pass(unsigned* L, int& m, int& rank,
                                              int shift, int lane)
{
    const unsigned bin = lane & 15;
    const unsigned r0 = (bin & 1) ? ~0u : 0u;
    const unsigned r1 = (bin & 2) ? ~0u : 0u;
    const unsigned r2 = (bin & 4) ? ~0u : 0u;
    const unsigned r3 = (bin & 8) ? ~0u : 0u;
    const unsigned lt = (1u << lane) - 1u;
    int iters = (m + 31) >> 5;
    int cnt = 0;
    for (int i = 0; i < iters; i++) {
        int idx = i * 32 + lane;
        bool act = idx < m;
        unsigned u = act ? L[idx] : 0u;
        unsigned d = u >> shift;
        unsigned B0 = __ballot_sync(~0u, act && (d & 1));
        unsigned B1 = __ballot_sync(~0u, act && (d & 2));
        unsigned B2 = __ballot_sync(~0u, act && (d & 4));
        unsigned B3 = __ballot_sync(~0u, act && (d & 8));
        unsigned A  = __ballot_sync(~0u, act);
        unsigned mm = A & ~((B3 ^ r3) | (B2 ^ r2) | (B1 ^ r1) | (B0 ^ r0));
        cnt += __popc(mm);
    }
    int incl = cnt;
    #pragma unroll
    for (int o = 1; o < 16; o <<= 1) {
        int n = __shfl_up_sync(~0u, incl, o, 16);
        if ((lane & 15) >= o) incl += n;
    }
    int excl = incl - cnt;
    bool hit = (lane < 16) && (rank >= excl) && (rank < incl);
    unsigned bal = __ballot_sync(~0u, hit);
    int src = __ffs(bal) - 1;
    unsigned dig = (unsigned)src;
    int nr = rank - excl;
    rank = __shfl_sync(~0u, nr, src);
    int w = 0;
    for (int i = 0; i < iters; i++) {
        int idx = i * 32 + lane;
        bool act = idx < m;
        unsigned u = act ? L[idx] : 0u;
        bool keep = act && (((u >> shift) & 15u) == dig);
        unsigned kb = __ballot_sync(~0u, keep);
        if (keep) L[w + __popc(kb & lt)] = u;
        w += __popc(kb);
    }
    m = w;
    return dig;
}

__device__ __forceinline__ unsigned final32(const unsigned* L, int m, int rank, int lane)
{
    unsigned myv = (lane < m) ? L[lane] : 0xFFFFFFFFu;
    int c = 0;
    #pragma unroll
    for (int j = 0; j < 32; j++) {
        unsigned o = __shfl_sync(~0u, myv, j);
        c += (o < myv) || (o == myv && j < lane);
    }
    bool hit = (c == rank) && (lane < m);
    unsigned bal = __ballot_sync(~0u, hit);
    int src = __ffs(bal) - 1;
    return __shfl_sync(~0u, myv, src);
}

__device__ __forceinline__ unsigned solve_list(unsigned* L, int m, int rank,
                                               unsigned tp, int sh0, int lane)
{
    int sh = sh0, m_ = m, r = rank; unsigned tp_ = tp;
    while (m_ > 32 && sh >= 0) {
        unsigned d = list_pass(L, m_, r, sh, lane);
        tp_ |= d << sh; sh -= 4;
    }
    return (m_ > 32) ? tp_ : final32(L, m_, r, lane);
}

// ---- fast path helpers ----
// Packed 16-bin hist over a private segment; narrows rank to one 4-bit digit.
// All lanes return identical (dig, r, m).
__device__ __forceinline__ void level16(const unsigned* seg, int n,
                                        unsigned pmask, unsigned pfx, int shift,
                                        int& r, int& m, unsigned& dig)
{
    unsigned h[8];
    #pragma unroll
    for (int k = 0; k < 8; k++) h[k] = 0u;
    for (int i = 0; i < n; i++) {
        unsigned u = seg[i];
        if ((u & pmask) == pfx) {
            int d = (u >> shift) & 15;
            h[d >> 1] += 1u << ((d & 1) << 4);
        }
    }
    #pragma unroll
    for (int k = 0; k < 8; k++) h[k] = (unsigned)wsum((int)h[k]);
    int run = 0, d = -1, rn = 0, mm = 0;
    #pragma unroll
    for (int b = 0; b < 16; b++) {
        int c = (int)((h[b >> 1] >> ((b & 1) << 4)) & 0xFFFFu);
        if (d < 0 && r < run + c) { d = b; rn = r - run; mm = c; }
        run += c;
    }
    dig = (unsigned)d; r = rn; m = mm;
}

__device__ __forceinline__ int extract_seg(const unsigned* seg, int n,
                                           unsigned pmask, unsigned pfx,
                                           unsigned* list, int lane)
{
    int mc = 0;
    for (int i = 0; i < n; i++) mc += ((seg[i] & pmask) == pfx);
    int incl = mc;
    #pragma unroll
    for (int o = 1; o < 32; o <<= 1) {
        int t = __shfl_up_sync(~0u, incl, o);
        if (lane >= o) incl += t;
    }
    int off = incl - mc;
    int tot = __shfl_sync(~0u, incl, 31);
    if (tot <= LIST_CAP) {
        int wp = off;
        for (int i = 0; i < n; i++) {
            unsigned u = seg[i];
            if ((u & pmask) == pfx) list[wp++] = u;
        }
    }
    return tot;
}

#define SEL_SMEM ((2048 + 4 * (2 * 32 * SEG_STRIDE) + 4 * 2 * LIST_CAP) * 4)

__global__ void __launch_bounds__(128) select_kernel(const float* __restrict__ bias)
{
    extern __shared__ float smem[];
    float* sbias = smem;                                   // 2048 floats
    unsigned* segs = (unsigned*)(smem + 2048);             // 4 warps * 2*32*SEG_STRIDE
    unsigned* lists = segs + 4 * (2 * 32 * SEG_STRIDE);    // 4 warps * 2*LIST_CAP

    const int tid = threadIdx.x;
    const int wid = tid >> 5, lane = tid & 31;

    {
        const float4* bsrc = (const float4*)bias;
        float4* bdst = (float4*)sbias;
        #pragma unroll
        for (int i = 0; i < 4; i++) bdst[tid + 128 * i] = bsrc[tid + 128 * i];
    }
    __syncthreads();

    const int pos = blockIdx.x * 4 + wid;
    const float4* vsrc = (const float4*)(g_conv + (size_t)pos * NC);
    unsigned* warpseg = segs + wid * (2 * 32 * SEG_STRIDE);
    unsigned* seg1 = warpseg + lane * SEG_STRIDE;
    unsigned* seg2 = warpseg + (32 + lane) * SEG_STRIDE;
    unsigned* list1 = lists + wid * 2 * LIST_CAP;
    unsigned* list2 = list1 + LIST_CAP;

    // ---- collective-free sweep: local count-below + private compaction ----
    int cb1 = 0, cb2 = 0, n1 = 0, n2 = 0;
    {
        const float4* bs4 = (const float4*)sbias;
        for (int t = 0; t < 16; t++) {
            float4 v4 = __ldg(vsrc + t * 32 + lane);
            float4 b4 = bs4[t * 32 + lane];
            #pragma unroll
            for (int e = 0; e < 4; e++) {
                float v = (&v4.x)[e], bb = (&b4.x)[e];
                unsigned u1 = f2u(bb - v), u2 = f2u(bb + v);
                cb1 += (u1 < T0);
                if (u1 - T0 < RNG) { if (n1 < SEG_CAP) seg1[n1] = u1; n1++; }
                cb2 += (u2 < T0);
                if (u2 - T0 < RNG) { if (n2 < SEG_CAP) seg2[n2] = u2; n2++; }
            }
        }
    }
    unsigned ovf = __ballot_sync(~0u, (n1 > SEG_CAP) || (n2 > SEG_CAP));
    int tb1 = wsum(cb1), tb2 = wsum(cb2);
    int tn1 = wsum(n1), tn2 = wsum(n2);
    int r1 = KSEL - tb1, r2 = KSEL - tb2;
    bool good = (ovf == 0u) && r1 >= 0 && r1 < tn1 && r2 >= 0 && r2 < tn2;

    unsigned ansu1 = 0, ansu2 = 0;
    if (good) {
        // branch 1: two packed-hist levels, then tiny exact list
        int rr = r1, m; unsigned d;
        level16(seg1, n1, 0xF0000000u, T0, 24, rr, m, d);
        unsigned pfx8 = T0 | (d << 24);
        level16(seg1, n1, 0xFF000000u, pfx8, 20, rr, m, d);
        unsigned pfx12 = pfx8 | (d << 20);
        int mt = extract_seg(seg1, n1, 0xFFF00000u, pfx12, list1, lane);
        if (mt > LIST_CAP) good = false;
        else ansu1 = solve_list(list1, mt, rr, pfx12, 16, lane);

        if (good) {
            int rr2 = r2, m2; unsigned d2;
            level16(seg2, n2, 0xF0000000u, T0, 24, rr2, m2, d2);
            unsigned p8 = T0 | (d2 << 24);
            level16(seg2, n2, 0xFF000000u, p8, 20, rr2, m2, d2);
            unsigned p12 = p8 | (d2 << 20);
            int mt2 = extract_seg(seg2, n2, 0xFFF00000u, p12, list2, lane);
            if (mt2 > LIST_CAP) good = false;
            else ansu2 = solve_list(list2, mt2, rr2, p12, 16, lane);
        }
    }
    if (!good) {
        // ---- exact general radix path (rare); reuse seg space as lists ----
        unsigned* l1 = warpseg;
        unsigned* l2 = warpseg + SEL_CAP;
        int rank1 = KSEL, rank2 = KSEL;
        unsigned top1 = 0, top2 = 0, maskTop = 0;
        int m1 = NC, m2 = NC;
        int shift = 28;
        unsigned dig1, dig2;
        {
            int cnt = hist_sweep<false>(vsrc, sbias, 0, 0, 0, shift, lane);
            pick_bins(cnt, rank1, rank2, dig1, dig2, m1, m2, lane);
            top1 |= dig1 << shift; top2 |= dig2 << shift;
            maskTop |= 0xFu << shift; shift -= 4;
        }
        while ((m1 > SEL_CAP || m2 > SEL_CAP) && shift >= 0) {
            int cnt = hist_sweep<true>(vsrc, sbias, top1, top2, maskTop, shift, lane);
            pick_bins(cnt, rank1, rank2, dig1, dig2, m1, m2, lane);
            top1 |= dig1 << shift; top2 |= dig2 << shift;
            maskTop |= 0xFu << shift; shift -= 4;
        }
        bool en1 = (m1 <= SEL_CAP), en2 = (m2 <= SEL_CAP);
        compact_sweep(vsrc, sbias, top1, top2, maskTop, l1, l2, en1, en2, lane);
        ansu1 = en1 ? solve_list(l1, m1, rank1, top1, shift, lane) : top1;
        ansu2 = en2 ? solve_list(l2, m2, rank2, top2, shift, lane) : top2;
    }

    if (lane == 0) {
        g_t1[pos] = u2f(ansu1);
        g_t2[pos] = u2f(ansu2);
    }
}

// ---------------------------------------------------------------------------
// Kernel 3: masks + (avg_pool_ceil(5,3) o adaptive(6)) as separable 6x27 map A.
// ---------------------------------------------------------------------------
__global__ void __launch_bounds__(128) pool_kernel(const float* __restrict__ bias,
                                                   float* __restrict__ out)
{
    __shared__ float st1[NPOS9], st2[NPOS9];
    __shared__ float sA[6][28];

    const int b = blockIdx.y;
    const int c = blockIdx.x * 128 + threadIdx.x;

    for (int i = threadIdx.x; i < NPOS9; i += 128) {
        st1[i] = g_t1[b * NPOS9 + i];
        st2[i] = g_t2[b * NPOS9 + i];
    }
    if (threadIdx.x < 27) {
        int wcol = threadIdx.x;
        const int sidx[6] = {0, 1, 3, 4, 6, 7};
        #pragma unroll
        for (int i = 0; i < 6; i++) {
            float a = 0.0f;
            #pragma unroll
            for (int q = 0; q < 2; q++) {
                int p = sidx[i] + q;
                int st = 3 * p, en = (st + 5 < 27) ? st + 5 : 27;
                if (wcol >= st && wcol < en) a += 0.5f / (float)(en - st);
            }
            sA[i][wcol] = a;
        }
    }
    __syncthreads();

    const float bc = bias[c];
    const float* p = g_conv + (size_t)b * NPOS9 * NC + c;

    float acc1[36], acc2[36];
    #pragma unroll
    for (int k = 0; k < 36; k++) { acc1[k] = 0.0f; acc2[k] = 0.0f; }

    int idx = 0;
    for (int h = 0; h < 27; h++) {
        float r1[6], r2[6];
        #pragma unroll
        for (int j = 0; j < 6; j++) { r1[j] = 0.0f; r2[j] = 0.0f; }
        for (int wcol = 0; wcol < 27; wcol++, idx++) {
            float v = __ldg(p + (size_t)idx * NC);
            float m1 = (bc - v < st1[idx]) ? 1.0f : 0.0f;
            float m2 = (bc + v < st2[idx]) ? 1.0f : 0.0f;
            #pragma unroll
            for (int j = 0; j < 6; j++) {
                float a = sA[j][wcol];
                r1[j] += a * m1;
                r2[j] += a * m2;
            }
        }
        #pragma unroll
        for (int i = 0; i < 6; i++) {
            float ah = sA[i][h];
            #pragma unroll
            for (int j = 0; j < 6; j++) {
                acc1[i * 6 + j] += ah * r1[j];
                acc2[i * 6 + j] += ah * r2[j];
            }
        }
    }

    float* o1 = out + ((size_t)(b * NC + c)) * 36;
    float* o2 = o1 + (size_t)NB * NC * 36;
    #pragma unroll
    for (int k = 0; k < 36; k++) { o1[k] = acc1[k]; o2[k] = acc2[k]; }
}

// ---------------------------------------------------------------------------
extern "C" void kernel_launch(void* const* d_in, const int* in_sizes, int n_in,
                              void* d_out, int out_size)
{
    const float* x    = (const float*)d_in[0]; // [64,3,32,32]
    const float* w    = (const float*)d_in[1]; // [2048,3,6,6]
    const float* bias = (const float*)d_in[2]; // [2048]
    float* out = (float*)d_out;                // [2][64,2048,6,6]

    cudaFuncSetAttribute(conv_kernel, cudaFuncAttributeMaxDynamicSharedMemorySize, CONV_SMEM);
    cudaFuncSetAttribute(select_kernel, cudaFuncAttributeMaxDynamicSharedMemorySize, SEL_SMEM);

    conv_kernel<<<dim3(16, 64), 256, CONV_SMEM>>>(x, w);
    select_kernel<<<TOTPOS / 4, 128, SEL_SMEM>>>(bias);
    pool_kernel<<<dim3(16, 64), 128>>>(bias, out);
}

// round 8
// speedup vs baseline: 1.2926x; 1.2926x over previous
#include <cuda_runtime.h>
#include <cstdint>

#define NB 64
#define NC 2048
#define NPOS9 729          // 27*27
#define TOTPOS (NB*NPOS9)  // 46656
#define KSEL 819
#define SEL_CAP 1024
#define T0 0x40000000u
#define RNG 0x10000000u

__device__ float g_conv[(size_t)NB * NPOS9 * NC];  // NHWC: [b][p][c]
__device__ float g_t1[TOTPOS];
__device__ float g_t2[TOTPOS];

// ---------------------------------------------------------------------------
// Kernel 1: conv (VALID, stride 1) -> NHWC scratch.  fp32 via fma.rn.f32x2.
// ---------------------------------------------------------------------------
#define CONV_XS2_U64 3072
#define CONV_W_U64  (108 * 4 * 16)
#define CONV_SMEM ((CONV_XS2_U64 + CONV_W_U64) * 8)

__global__ void __launch_bounds__(256) conv_kernel(const float* __restrict__ x,
                                                   const float* __restrict__ w)
{
    extern __shared__ unsigned long long smem64[];
    float2* xs2 = (float2*)smem64;                       // 3072 pairs {x,x}
    float2* ws2 = (float2*)(smem64 + CONV_XS2_U64);      // 6912 weight pairs
    const unsigned long long* xsu = smem64;
    const unsigned long long* wsu = smem64 + CONV_XS2_U64;

    const int b = blockIdx.y;
    const int c0 = blockIdx.x * 128;
    const int tid = threadIdx.x;

    {
        const float* xsrc = x + (size_t)b * 3072;
        #pragma unroll
        for (int i = 0; i < 12; i++) {
            int idx = tid + 256 * i;
            float v = xsrc[idx];
            xs2[idx] = make_float2(v, v);
        }
    }
    for (int idx = tid; idx < CONV_W_U64; idx += 256) {
        int ct = idx & 15;
        int kq = idx >> 4;
        int k = kq >> 2, q = kq & 3;
        int ch = c0 + ct * 8 + 2 * q;
        float a = w[(size_t)ch * 108 + k];
        float bb = w[(size_t)(ch + 1) * 108 + k];
        ws2[idx] = make_float2(a, bb);
    }
    __syncthreads();

    const int ch_tid = tid & 15;
    const int pos_tid = tid >> 4;
    const int ch0 = ch_tid * 8;

    for (int chunk = 0; chunk < 6; chunk++) {
        const int p0 = chunk * 128 + pos_tid * 8;
        int pbase[8];
        #pragma unroll
        for (int pp = 0; pp < 8; pp++) {
            int p = p0 + pp; if (p > 728) p = 728;
            int y = p / 27;
            pbase[pp] = y * 32 + (p - y * 27);
        }
        unsigned long long acc0[8], acc1[8], acc2[8], acc3[8];
        #pragma unroll
        for (int pp = 0; pp < 8; pp++) { acc0[pp] = 0ull; acc1[pp] = 0ull; acc2[pp] = 0ull; acc3[pp] = 0ull; }

        #pragma unroll 1
        for (int c = 0; c < 3; c++) {
            #pragma unroll 1
            for (int i = 0; i < 6; i++) {
                const unsigned long long* xrow = xsu + c * 1024 + i * 32;
                const int kbase = (c * 36 + i * 6) * 4;
                #pragma unroll
                for (int j = 0; j < 6; j++) {
                    const unsigned long long* wk = wsu + (size_t)(kbase + j * 4) * 16 + ch_tid;
                    unsigned long long w0 = wk[0], w1 = wk[16], w2 = wk[32], w3 = wk[48];
                    #pragma unroll
                    for (int pp = 0; pp < 8; pp++) {
                        unsigned long long xx = xrow[pbase[pp] + j];
                        asm("fma.rn.f32x2 %0, %1, %2, %0;" : "+l"(acc0[pp]) : "l"(w0), "l"(xx));
                        asm("fma.rn.f32x2 %0, %1, %2, %0;" : "+l"(acc1[pp]) : "l"(w1), "l"(xx));
                        asm("fma.rn.f32x2 %0, %1, %2, %0;" : "+l"(acc2[pp]) : "l"(w2), "l"(xx));
                        asm("fma.rn.f32x2 %0, %1, %2, %0;" : "+l"(acc3[pp]) : "l"(w3), "l"(xx));
                    }
                }
            }
        }
        #pragma unroll
        for (int pp = 0; pp < 8; pp++) {
            int p = p0 + pp;
            if (p < 729) {
                float* dst = g_conv + ((size_t)(b * NPOS9 + p)) * NC + c0 + ch0;
                float a, bb, cc, dd, e, f, g, h;
                asm("mov.b64 {%0, %1}, %2;" : "=f"(a), "=f"(bb) : "l"(acc0[pp]));
                asm("mov.b64 {%0, %1}, %2;" : "=f"(cc), "=f"(dd) : "l"(acc1[pp]));
                asm("mov.b64 {%0, %1}, %2;" : "=f"(e), "=f"(f) : "l"(acc2[pp]));
                asm("mov.b64 {%0, %1}, %2;" : "=f"(g), "=f"(h) : "l"(acc3[pp]));
                ((float4*)dst)[0] = make_float4(a, bb, cc, dd);
                ((float4*)dst)[1] = make_float4(e, f, g, h);
            }
        }
    }
}

// ---------------------------------------------------------------------------
// Kernel 2: speculative single-sweep select (batched loads, MLP=8) + fallback.
// ---------------------------------------------------------------------------
__device__ __forceinline__ unsigned f2u(float f) {
    int b = __float_as_int(f);
    return (unsigned)(b ^ ((b >> 31) | 0x80000000));
}
__device__ __forceinline__ float u2f(unsigned u) {
    unsigned b = (u & 0x80000000u) ? (u & 0x7fffffffu) : ~u;
    return __uint_as_float(b);
}

template<bool MASKED>
__device__ __forceinline__ int hist_sweep(const float4* __restrict__ vsrc,
                                          const float* __restrict__ sbias,
                                          unsigned top1, unsigned top2,
                                          unsigned maskTop, int shift, int lane)
{
    const unsigned bin = lane & 15;
    const unsigned r0 = (bin & 1) ? ~0u : 0u;
    const unsigned r1 = (bin & 2) ? ~0u : 0u;
    const unsigned r2 = (bin & 4) ? ~0u : 0u;
    const unsigned r3 = (bin & 8) ? ~0u : 0u;
    const bool br2 = (lane >= 16);
    int cnt = 0;
    const float4* bs4 = (const float4*)sbias;
    #pragma unroll 1
    for (int half = 0; half < 2; half++) {
        float4 vv[8], bv[8];
        #pragma unroll
        for (int t = 0; t < 8; t++) {
            vv[t] = __ldg(vsrc + (half * 8 + t) * 32 + lane);
            bv[t] = bs4[(half * 8 + t) * 32 + lane];
        }
        #pragma unroll
        for (int t = 0; t < 8; t++) {
            #pragma unroll
            for (int e = 0; e < 4; e++) {
                float v = (&vv[t].x)[e], bb = (&bv[t].x)[e];
                unsigned u1 = f2u(bb - v), u2 = f2u(bb + v);
                bool a1 = MASKED ? (((u1 ^ top1) & maskTop) == 0) : true;
                bool a2 = MASKED ? (((u2 ^ top2) & maskTop) == 0) : true;
                unsigned d1 = u1 >> shift, d2 = u2 >> shift;
                unsigned B10 = __ballot_sync(~0u, a1 && (d1 & 1));
                unsigned B11 = __ballot_sync(~0u, a1 && (d1 & 2));
                unsigned B12 = __ballot_sync(~0u, a1 && (d1 & 4));
                unsigned B13 = __ballot_sync(~0u, a1 && (d1 & 8));
                unsigned A1  = MASKED ? __ballot_sync(~0u, a1) : ~0u;
                unsigned B20 = __ballot_sync(~0u, a2 && (d2 & 1));
                unsigned B21 = __ballot_sync(~0u, a2 && (d2 & 2));
                unsigned B22 = __ballot_sync(~0u, a2 && (d2 & 4));
                unsigned B23 = __ballot_sync(~0u, a2 && (d2 & 8));
                unsigned A2  = MASKED ? __ballot_sync(~0u, a2) : ~0u;
                unsigned Bb0 = br2 ? B20 : B10;
                unsigned Bb1 = br2 ? B21 : B11;
                unsigned Bb2 = br2 ? B22 : B12;
                unsigned Bb3 = br2 ? B23 : B13;
                unsigned A   = br2 ? A2  : A1;
                unsigned mm = A & ~((Bb3 ^ r3) | (Bb2 ^ r2) | (Bb1 ^ r1) | (Bb0 ^ r0));
                cnt += __popc(mm);
            }
        }
    }
    return cnt;
}

__device__ __forceinline__ void pick_bins(int cnt, int& rank1, int& rank2,
                                          unsigned& dig1, unsigned& dig2,
                                          int& m1, int& m2, int lane)
{
    int incl = cnt;
    #pragma unroll
    for (int o = 1; o < 16; o <<= 1) {
        int n = __shfl_up_sync(~0u, incl, o, 16);
        if ((lane & 15) >= o) incl += n;
    }
    int excl = incl - cnt;
    int rk = (lane < 16) ? rank1 : rank2;
    bool hit = (rk >= excl) && (rk < incl);
    unsigned bal = __ballot_sync(~0u, hit);
    int src1 = __ffs(bal & 0xFFFFu) - 1;
    int src2 = 31 - __clz(bal & 0xFFFF0000u);
    int nr = rk - excl;
    dig1 = (unsigned)(src1 & 15);
    dig2 = (unsigned)(src2 & 15);
    rank1 = __shfl_sync(~0u, nr, src1);
    rank2 = __shfl_sync(~0u, nr, src2);
    m1 = __shfl_sync(~0u, cnt, src1);
    m2 = __shfl_sync(~0u, cnt, src2);
}

__device__ __forceinline__ void compact_sweep(const float4* __restrict__ vsrc,
                                              const float* __restrict__ sbias,
                                              unsigned top1, unsigned top2,
                                              unsigned maskTop,
                                              unsigned* l1, unsigned* l2,
                                              bool en1, bool en2, int lane)
{
    int n1 = 0, n2 = 0;
    const unsigned lt = (1u << lane) - 1u;
    const float4* bs4 = (const float4*)sbias;
    #pragma unroll 1
    for (int half = 0; half < 2; half++) {
        float4 vv[8], bv[8];
        #pragma unroll
        for (int t = 0; t < 8; t++) {
            vv[t] = __ldg(vsrc + (half * 8 + t) * 32 + lane);
            bv[t] = bs4[(half * 8 + t) * 32 + lane];
        }
        #pragma unroll
        for (int t = 0; t < 8; t++) {
            #pragma unroll
            for (int e = 0; e < 4; e++) {
                float v = (&vv[t].x)[e], bb = (&bv[t].x)[e];
                unsigned u1 = f2u(bb - v), u2 = f2u(bb + v);
                bool k1 = en1 && (((u1 ^ top1) & maskTop) == 0);
                bool k2 = en2 && (((u2 ^ top2) & maskTop) == 0);
                unsigned bal1 = __ballot_sync(~0u, k1);
                if (k1) l1[n1 + __popc(bal1 & lt)] = u1;
                n1 += __popc(bal1);
                unsigned bal2 = __ballot_sync(~0u, k2);
                if (k2) l2[n2 + __popc(bal2 & lt)] = u2;
                n2 += __popc(bal2);
            }
        }
    }
}

__device__ __forceinline__ unsigned list_pass(unsigned* L, int& m, int& rank,
                                              int shift, int lane)
{
    const unsigned bin = lane & 15;
    const unsigned r0 = (bin & 1) ? ~0u : 0u;
    const unsigned r1 = (bin & 2) ? ~0u : 0u;
    const unsigned r2 = (bin & 4) ? ~0u : 0u;
    const unsigned r3 = (bin & 8) ? ~0u : 0u;
    const unsigned lt = (1u << lane) - 1u;
    int iters = (m + 31) >> 5;
    int cnt = 0;
    for (int i = 0; i < iters; i++) {
        int idx = i * 32 + lane;
        bool act = idx < m;
        unsigned u = act ? L[idx] : 0u;
        unsigned d = u >> shift;
        unsigned B0 = __ballot_sync(~0u, act && (d & 1));
        unsigned B1 = __ballot_sync(~0u, act && (d & 2));
        unsigned B2 = __ballot_sync(~0u, act && (d & 4));
        unsigned B3 = __ballot_sync(~0u, act && (d & 8));
        unsigned A  = __ballot_sync(~0u, act);
        unsigned mm = A & ~((B3 ^ r3) | (B2 ^ r2) | (B1 ^ r1) | (B0 ^ r0));
        cnt += __popc(mm);
    }
    int incl = cnt;
    #pragma unroll
    for (int o = 1; o < 16; o <<= 1) {
        int n = __shfl_up_sync(~0u, incl, o, 16);
        if ((lane & 15) >= o) incl += n;
    }
    int excl = incl - cnt;
    bool hit = (lane < 16) && (rank >= excl) && (rank < incl);
    unsigned bal = __ballot_sync(~0u, hit);
    int src = __ffs(bal) - 1;
    unsigned dig = (unsigned)src;
    int nr = rank - excl;
    rank = __shfl_sync(~0u, nr, src);
    int w = 0;
    for (int i = 0; i < iters; i++) {
        int idx = i * 32 + lane;
        bool act = idx < m;
        unsigned u = act ? L[idx] : 0u;
        bool keep = act && (((u >> shift) & 15u) == dig);
        unsigned kb = __ballot_sync(~0u, keep);
        if (keep) L[w + __popc(kb & lt)] = u;
        w += __popc(kb);
    }
    m = w;
    return dig;
}

__device__ __forceinline__ unsigned final32(const unsigned* L, int m, int rank, int lane)
{
    unsigned myv = (lane < m) ? L[lane] : 0xFFFFFFFFu;
    int c = 0;
    #pragma unroll
    for (int j = 0; j < 32; j++) {
        unsigned o = __shfl_sync(~0u, myv, j);
        c += (o < myv) || (o == myv && j < lane);
    }
    bool hit = (c == rank) && (lane < m);
    unsigned bal = __ballot_sync(~0u, hit);
    int src = __ffs(bal) - 1;
    return __shfl_sync(~0u, myv, src);
}

__device__ __forceinline__ unsigned solve_list(unsigned* L, int m, int rank,
                                               unsigned tp, int sh0, int lane)
{
    int sh = sh0, m_ = m, r = rank; unsigned tp_ = tp;
    while (m_ > 32 && sh >= 0) {
        unsigned d = list_pass(L, m_, r, sh, lane);
        tp_ |= d << sh; sh -= 4;
    }
    return (m_ > 32) ? tp_ : final32(L, m_, r, lane);
}

#define SEL_SMEM (2048 * 4 + 4 * 2 * SEL_CAP * 4)

__global__ void __launch_bounds__(128) select_kernel(const float* __restrict__ bias)
{
    extern __shared__ float smem[];
    float* sbias = smem;                          // 2048 floats
    unsigned* slist = (unsigned*)(smem + 2048);   // 4 warps * 2 * SEL_CAP

    const int tid = threadIdx.x;
    const int wid = tid >> 5, lane = tid & 31;

    {
        const float4* bsrc = (const float4*)bias;
        float4* bdst = (float4*)sbias;
        #pragma unroll
        for (int i = 0; i < 4; i++) bdst[tid + 128 * i] = bsrc[tid + 128 * i];
    }
    __syncthreads();

    const int pos = blockIdx.x * 4 + wid;
    const float4* vsrc = (const float4*)(g_conv + (size_t)pos * NC);
    unsigned* l1 = slist + wid * 2 * SEL_CAP;
    unsigned* l2 = l1 + SEL_CAP;

    // ---- speculative fused sweep with batched loads (MLP=8) ----
    const unsigned lt = (1u << lane) - 1u;
    int cb1 = 0, cb2 = 0;     // # keys < T0
    int n1 = 0, n2 = 0;       // # keys in [T0, T0+RNG)
    {
        const float4* bs4 = (const float4*)sbias;
        #pragma unroll 1
        for (int half = 0; half < 2; half++) {
            float4 vv[8], bv[8];
            #pragma unroll
            for (int t = 0; t < 8; t++) {
                vv[t] = __ldg(vsrc + (half * 8 + t) * 32 + lane);
                bv[t] = bs4[(half * 8 + t) * 32 + lane];
            }
            #pragma unroll
            for (int t = 0; t < 8; t++) {
                #pragma unroll
                for (int e = 0; e < 4; e++) {
                    float v = (&vv[t].x)[e], bb = (&bv[t].x)[e];
                    unsigned u1 = f2u(bb - v), u2 = f2u(bb + v);
                    bool below1 = u1 < T0;
                    bool in1 = (u1 - T0) < RNG;
                    bool below2 = u2 < T0;
                    bool in2 = (u2 - T0) < RNG;
                    cb1 += __popc(__ballot_sync(~0u, below1));
                    unsigned bi1 = __ballot_sync(~0u, in1);
                    if (in1) { int ix = n1 + __popc(bi1 & lt); if (ix < SEL_CAP) l1[ix] = u1; }
                    n1 += __popc(bi1);
                    cb2 += __popc(__ballot_sync(~0u, below2));
                    unsigned bi2 = __ballot_sync(~0u, in2);
                    if (in2) { int ix = n2 + __popc(bi2 & lt); if (ix < SEL_CAP) l2[ix] = u2; }
                    n2 += __popc(bi2);
                }
            }
        }
    }
    int r1 = KSEL - cb1, r2 = KSEL - cb2;
    bool ok1 = (r1 >= 0) && (r1 < n1) && (n1 <= SEL_CAP);
    bool ok2 = (r2 >= 0) && (r2 < n2) && (n2 <= SEL_CAP);

    unsigned ansu1, ansu2;
    if (ok1 && ok2) {
        ansu1 = solve_list(l1, n1, r1, T0, 24, lane);
        ansu2 = solve_list(l2, n2, r2, T0, 24, lane);
    } else {
        // ---- exact general radix path (rare) ----
        int rank1 = KSEL, rank2 = KSEL;
        unsigned top1 = 0, top2 = 0, maskTop = 0;
        int m1 = NC, m2 = NC;
        int shift = 28;
        unsigned dig1, dig2;
        {
            int cnt = hist_sweep<false>(vsrc, sbias, 0, 0, 0, shift, lane);
            pick_bins(cnt, rank1, rank2, dig1, dig2, m1, m2, lane);
            top1 |= dig1 << shift; top2 |= dig2 << shift;
            maskTop |= 0xFu << shift; shift -= 4;
        }
        while ((m1 > SEL_CAP || m2 > SEL_CAP) && shift >= 0) {
            int cnt = hist_sweep<true>(vsrc, sbias, top1, top2, maskTop, shift, lane);
            pick_bins(cnt, rank1, rank2, dig1, dig2, m1, m2, lane);
            top1 |= dig1 << shift; top2 |= dig2 << shift;
            maskTop |= 0xFu << shift; shift -= 4;
        }
        bool en1 = (m1 <= SEL_CAP), en2 = (m2 <= SEL_CAP);
        compact_sweep(vsrc, sbias, top1, top2, maskTop, l1, l2, en1, en2, lane);
        ansu1 = en1 ? solve_list(l1, m1, rank1, top1, shift, lane) : top1;
        ansu2 = en2 ? solve_list(l2, m2, rank2, top2, shift, lane) : top2;
    }

    if (lane == 0) {
        g_t1[pos] = u2f(ansu1);
        g_t2[pos] = u2f(ansu2);
    }
}

// ---------------------------------------------------------------------------
// Kernel 3: masks + (avg_pool_ceil(5,3) o adaptive(6)) as separable 6x27 map A.
// ---------------------------------------------------------------------------
__global__ void __launch_bounds__(128) pool_kernel(const float* __restrict__ bias,
                                                   float* __restrict__ out)
{
    __shared__ float st1[NPOS9], st2[NPOS9];
    __shared__ float sA[6][28];

    const int b = blockIdx.y;
    const int c = blockIdx.x * 128 + threadIdx.x;

    for (int i = threadIdx.x; i < NPOS9; i += 128) {
        st1[i] = g_t1[b * NPOS9 + i];
        st2[i] = g_t2[b * NPOS9 + i];
    }
    if (threadIdx.x < 27) {
        int wcol = threadIdx.x;
        const int sidx[6] = {0, 1, 3, 4, 6, 7};
        #pragma unroll
        for (int i = 0; i < 6; i++) {
            float a = 0.0f;
            #pragma unroll
            for (int q = 0; q < 2; q++) {
                int p = sidx[i] + q;
                int st = 3 * p, en = (st + 5 < 27) ? st + 5 : 27;
                if (wcol >= st && wcol < en) a += 0.5f / (float)(en - st);
            }
            sA[i][wcol] = a;
        }
    }
    __syncthreads();

    const float bc = bias[c];
    const float* p = g_conv + (size_t)b * NPOS9 * NC + c;

    float acc1[36], acc2[36];
    #pragma unroll
    for (int k = 0; k < 36; k++) { acc1[k] = 0.0f; acc2[k] = 0.0f; }

    int idx = 0;
    for (int h = 0; h < 27; h++) {
        float r1[6], r2[6];
        #pragma unroll
        for (int j = 0; j < 6; j++) { r1[j] = 0.0f; r2[j] = 0.0f; }
        for (int wcol = 0; wcol < 27; wcol++, idx++) {
            float v = __ldg(p + (size_t)idx * NC);
            float m1 = (bc - v < st1[idx]) ? 1.0f : 0.0f;
            float m2 = (bc + v < st2[idx]) ? 1.0f : 0.0f;
            #pragma unroll
            for (int j = 0; j < 6; j++) {
                float a = sA[j][wcol];
                r1[j] += a * m1;
                r2[j] += a * m2;
            }
        }
        #pragma unroll
        for (int i = 0; i < 6; i++) {
            float ah = sA[i][h];
            #pragma unroll
            for (int j = 0; j < 6; j++) {
                acc1[i * 6 + j] += ah * r1[j];
                acc2[i * 6 + j] += ah * r2[j];
            }
        }
    }

    float* o1 = out + ((size_t)(b * NC + c)) * 36;
    float* o2 = o1 + (size_t)NB * NC * 36;
    #pragma unroll
    for (int k = 0; k < 36; k++) { o1[k] = acc1[k]; o2[k] = acc2[k]; }
}

// ---------------------------------------------------------------------------
extern "C" void kernel_launch(void* const* d_in, const int* in_sizes, int n_in,
                              void* d_out, int out_size)
{
    const float* x    = (const float*)d_in[0]; // [64,3,32,32]
    const float* w    = (const float*)d_in[1]; // [2048,3,6,6]
    const float* bias = (const float*)d_in[2]; // [2048]
    float* out = (float*)d_out;                // [2][64,2048,6,6]

    cudaFuncSetAttribute(conv_kernel, cudaFuncAttributeMaxDynamicSharedMemorySize, CONV_SMEM);
    cudaFuncSetAttribute(select_kernel, cudaFuncAttributeMaxDynamicSharedMemorySize, SEL_SMEM);

    conv_kernel<<<dim3(16, 64), 256, CONV_SMEM>>>(x, w);
    select_kernel<<<TOTPOS / 4, 128, SEL_SMEM>>>(bias);
    pool_kernel<<<dim3(16, 64), 128>>>(bias, out);
}

// round 9
// speedup vs baseline: 1.3130x; 1.0158x over previous
#include <cuda_runtime.h>
#include <cstdint>

#define NB 64
#define NC 2048
#define NPOS9 729          // 27*27
#define TOTPOS (NB*NPOS9)  // 46656
#define KSEL 819
#define SEL_CAP 512
#define WIN 0.28f

__device__ float g_conv[(size_t)NB * NPOS9 * NC];  // NHWC: [b][p][c]
__device__ float g_t1[TOTPOS];
__device__ float g_t2[TOTPOS];
__device__ float g_t0;

// ---------------------------------------------------------------------------
// Kernel 1: conv (VALID, stride 1) -> NHWC scratch.  fp32 via fma.rn.f32x2.
// ---------------------------------------------------------------------------
#define CONV_XS2_U64 3072
#define CONV_W_U64  (108 * 4 * 16)
#define CONV_SMEM ((CONV_XS2_U64 + CONV_W_U64) * 8)

__global__ void __launch_bounds__(256) conv_kernel(const float* __restrict__ x,
                                                   const float* __restrict__ w)
{
    extern __shared__ unsigned long long smem64[];
    float2* xs2 = (float2*)smem64;                       // 3072 pairs {x,x}
    float2* ws2 = (float2*)(smem64 + CONV_XS2_U64);      // 6912 weight pairs
    const unsigned long long* xsu = smem64;
    const unsigned long long* wsu = smem64 + CONV_XS2_U64;

    const int b = blockIdx.y;
    const int c0 = blockIdx.x * 128;
    const int tid = threadIdx.x;

    {
        const float* xsrc = x + (size_t)b * 3072;
        #pragma unroll
        for (int i = 0; i < 12; i++) {
            int idx = tid + 256 * i;
            float v = xsrc[idx];
            xs2[idx] = make_float2(v, v);
        }
    }
    for (int idx = tid; idx < CONV_W_U64; idx += 256) {
        int ct = idx & 15;
        int kq = idx >> 4;
        int k = kq >> 2, q = kq & 3;
        int ch = c0 + ct * 8 + 2 * q;
        float a = w[(size_t)ch * 108 + k];
        float bb = w[(size_t)(ch + 1) * 108 + k];
        ws2[idx] = make_float2(a, bb);
    }
    __syncthreads();

    const int ch_tid = tid & 15;
    const int pos_tid = tid >> 4;
    const int ch0 = ch_tid * 8;

    for (int chunk = 0; chunk < 6; chunk++) {
        const int p0 = chunk * 128 + pos_tid * 8;
        int pbase[8];
        #pragma unroll
        for (int pp = 0; pp < 8; pp++) {
            int p = p0 + pp; if (p > 728) p = 728;
            int y = p / 27;
            pbase[pp] = y * 32 + (p - y * 27);
        }
        unsigned long long acc0[8], acc1[8], acc2[8], acc3[8];
        #pragma unroll
        for (int pp = 0; pp < 8; pp++) { acc0[pp] = 0ull; acc1[pp] = 0ull; acc2[pp] = 0ull; acc3[pp] = 0ull; }

        #pragma unroll 1
        for (int c = 0; c < 3; c++) {
            #pragma unroll 1
            for (int i = 0; i < 6; i++) {
                const unsigned long long* xrow = xsu + c * 1024 + i * 32;
                const int kbase = (c * 36 + i * 6) * 4;
                #pragma unroll
                for (int j = 0; j < 6; j++) {
                    const unsigned long long* wk = wsu + (size_t)(kbase + j * 4) * 16 + ch_tid;
                    unsigned long long w0 = wk[0], w1 = wk[16], w2 = wk[32], w3 = wk[48];
                    #pragma unroll
                    for (int pp = 0; pp < 8; pp++) {
                        unsigned long long xx = xrow[pbase[pp] + j];
                        asm("fma.rn.f32x2 %0, %1, %2, %0;" : "+l"(acc0[pp]) : "l"(w0), "l"(xx));
                        asm("fma.rn.f32x2 %0, %1, %2, %0;" : "+l"(acc1[pp]) : "l"(w1), "l"(xx));
                        asm("fma.rn.f32x2 %0, %1, %2, %0;" : "+l"(acc2[pp]) : "l"(w2), "l"(xx));
                        asm("fma.rn.f32x2 %0, %1, %2, %0;" : "+l"(acc3[pp]) : "l"(w3), "l"(xx));
                    }
                }
            }
        }
        #pragma unroll
        for (int pp = 0; pp < 8; pp++) {
            int p = p0 + pp;
            if (p < 729) {
                float* dst = g_conv + ((size_t)(b * NPOS9 + p)) * NC + c0 + ch0;
                float a, bb, cc, dd, e, f, g, h;
                asm("mov.b64 {%0, %1}, %2;" : "=f"(a), "=f"(bb) : "l"(acc0[pp]));
                asm("mov.b64 {%0, %1}, %2;" : "=f"(cc), "=f"(dd) : "l"(acc1[pp]));
                asm("mov.b64 {%0, %1}, %2;" : "=f"(e), "=f"(f) : "l"(acc2[pp]));
                asm("mov.b64 {%0, %1}, %2;" : "=f"(g), "=f"(h) : "l"(acc3[pp]));
                ((float4*)dst)[0] = make_float4(a, bb, cc, dd);
                ((float4*)dst)[1] = make_float4(e, f, g, h);
            }
        }
    }
}

// ---------------------------------------------------------------------------
// select helpers
// ---------------------------------------------------------------------------
__device__ __forceinline__ unsigned f2u(float f) {
    int b = __float_as_int(f);
    return (unsigned)(b ^ ((b >> 31) | 0x80000000));
}
__device__ __forceinline__ float u2f(unsigned u) {
    unsigned b = (u & 0x80000000u) ? (u & 0x7fffffffu) : ~u;
    return __uint_as_float(b);
}
__device__ __forceinline__ int wsum(int v) {
    #pragma unroll
    for (int o = 16; o; o >>= 1) v += __shfl_xor_sync(~0u, v, o);
    return v;
}

template<bool MASKED>
__device__ __forceinline__ int hist_sweep(const float4* __restrict__ vsrc,
                                          const float* __restrict__ sbias,
                                          unsigned top1, unsigned top2,
                                          unsigned maskTop, int shift, int lane)
{
    const unsigned bin = lane & 15;
    const unsigned r0 = (bin & 1) ? ~0u : 0u;
    const unsigned r1 = (bin & 2) ? ~0u : 0u;
    const unsigned r2 = (bin & 4) ? ~0u : 0u;
    const unsigned r3 = (bin & 8) ? ~0u : 0u;
    const bool br2 = (lane >= 16);
    int cnt = 0;
    const float4* bs4 = (const float4*)sbias;
    for (int t = 0; t < 16; t++) {
        float4 v4 = __ldg(vsrc + t * 32 + lane);
        float4 b4 = bs4[t * 32 + lane];
        #pragma unroll
        for (int e = 0; e < 4; e++) {
            float v = (&v4.x)[e], bb = (&b4.x)[e];
            unsigned u1 = f2u(bb - v), u2 = f2u(bb + v);
            bool a1 = MASKED ? (((u1 ^ top1) & maskTop) == 0) : true;
            bool a2 = MASKED ? (((u2 ^ top2) & maskTop) == 0) : true;
            unsigned d1 = u1 >> shift, d2 = u2 >> shift;
            unsigned B10 = __ballot_sync(~0u, a1 && (d1 & 1));
            unsigned B11 = __ballot_sync(~0u, a1 && (d1 & 2));
            unsigned B12 = __ballot_sync(~0u, a1 && (d1 & 4));
            unsigned B13 = __ballot_sync(~0u, a1 && (d1 & 8));
            unsigned A1  = MASKED ? __ballot_sync(~0u, a1) : ~0u;
            unsigned B20 = __ballot_sync(~0u, a2 && (d2 & 1));
            unsigned B21 = __ballot_sync(~0u, a2 && (d2 & 2));
            unsigned B22 = __ballot_sync(~0u, a2 && (d2 & 4));
            unsigned B23 = __ballot_sync(~0u, a2 && (d2 & 8));
            unsigned A2  = MASKED ? __ballot_sync(~0u, a2) : ~0u;
            unsigned Bb0 = br2 ? B20 : B10;
            unsigned Bb1 = br2 ? B21 : B11;
            unsigned Bb2 = br2 ? B22 : B12;
            unsigned Bb3 = br2 ? B23 : B13;
            unsigned A   = br2 ? A2  : A1;
            unsigned mm = A & ~((Bb3 ^ r3) | (Bb2 ^ r2) | (Bb1 ^ r1) | (Bb0 ^ r0));
            cnt += __popc(mm);
        }
    }
    return cnt;
}

__device__ __forceinline__ void pick_bins(int cnt, int& rank1, int& rank2,
                                          unsigned& dig1, unsigned& dig2,
                                          int& m1, int& m2, int lane)
{
    int incl = cnt;
    #pragma unroll
    for (int o = 1; o < 16; o <<= 1) {
        int n = __shfl_up_sync(~0u, incl, o, 16);
        if ((lane & 15) >= o) incl += n;
    }
    int excl = incl - cnt;
    int rk = (lane < 16) ? rank1 : rank2;
    bool hit = (rk >= excl) && (rk < incl);
    unsigned bal = __ballot_sync(~0u, hit);
    int src1 = __ffs(bal & 0xFFFFu) - 1;
    int src2 = 31 - __clz(bal & 0xFFFF0000u);
    int nr = rk - excl;
    dig1 = (unsigned)(src1 & 15);
    dig2 = (unsigned)(src2 & 15);
    rank1 = __shfl_sync(~0u, nr, src1);
    rank2 = __shfl_sync(~0u, nr, src2);
    m1 = __shfl_sync(~0u, cnt, src1);
    m2 = __shfl_sync(~0u, cnt, src2);
}

__device__ __forceinline__ void compact_sweep(const float4* __restrict__ vsrc,
                                              const float* __restrict__ sbias,
                                              unsigned top1, unsigned top2,
                                              unsigned maskTop,
                                              unsigned* l1, unsigned* l2,
                                              bool en1, bool en2, int lane)
{
    int n1 = 0, n2 = 0;
    const unsigned lt = (1u << lane) - 1u;
    const float4* bs4 = (const float4*)sbias;
    for (int t = 0; t < 16; t++) {
        float4 v4 = __ldg(vsrc + t * 32 + lane);
        float4 b4 = bs4[t * 32 + lane];
        #pragma unroll
        for (int e = 0; e < 4; e++) {
            float v = (&v4.x)[e], bb = (&b4.x)[e];
            unsigned u1 = f2u(bb - v), u2 = f2u(bb + v);
            bool k1 = en1 && (((u1 ^ top1) & maskTop) == 0);
            bool k2 = en2 && (((u2 ^ top2) & maskTop) == 0);
            unsigned bal1 = __ballot_sync(~0u, k1);
            if (k1) l1[n1 + __popc(bal1 & lt)] = u1;
            n1 += __popc(bal1);
            unsigned bal2 = __ballot_sync(~0u, k2);
            if (k2) l2[n2 + __popc(bal2 & lt)] = u2;
            n2 += __popc(bal2);
        }
    }
}

__device__ __forceinline__ unsigned list_pass(unsigned* L, int& m, int& rank,
                                              int shift, int lane)
{
    const unsigned bin = lane & 15;
    const unsigned r0 = (bin & 1) ? ~0u : 0u;
    const unsigned r1 = (bin & 2) ? ~0u : 0u;
    const unsigned r2 = (bin & 4) ? ~0u : 0u;
    const unsigned r3 = (bin & 8) ? ~0u : 0u;
    const unsigned lt = (1u << lane) - 1u;
    int iters = (m + 31) >> 5;
    int cnt = 0;
    for (int i = 0; i < iters; i++) {
        int idx = i * 32 + lane;
        bool act = idx < m;
        unsigned u = act ? L[idx] : 0u;
        unsigned d = u >> shift;
        unsigned B0 = __ballot_sync(~0u, act && (d & 1));
        unsigned B1 = __ballot_sync(~0u, act && (d & 2));
        unsigned B2 = __ballot_sync(~0u, act && (d & 4));
        unsigned B3 = __ballot_sync(~0u, act && (d & 8));
        unsigned A  = __ballot_sync(~0u, act);
        unsigned mm = A & ~((B3 ^ r3) | (B2 ^ r2) | (B1 ^ r1) | (B0 ^ r0));
        cnt += __popc(mm);
    }
    int incl = cnt;
    #pragma unroll
    for (int o = 1; o < 16; o <<= 1) {
        int n = __shfl_up_sync(~0u, incl, o, 16);
        if ((lane & 15) >= o) incl += n;
    }
    int excl = incl - cnt;
    bool hit = (lane < 16) && (rank >= excl) && (rank < incl);
    unsigned bal = __ballot_sync(~0u, hit);
    int src = __ffs(bal) - 1;
    unsigned dig = (unsigned)src;
    int nr = rank - excl;
    rank = __shfl_sync(~0u, nr, src);
    int w = 0;
    for (int i = 0; i < iters; i++) {
        int idx = i * 32 + lane;
        bool act = idx < m;
        unsigned u = act ? L[idx] : 0u;
        bool keep = act && (((u >> shift) & 15u) == dig);
        unsigned kb = __ballot_sync(~0u, keep);
        if (keep) L[w + __popc(kb & lt)] = u;
        w += __popc(kb);
    }
    m = w;
    return dig;
}

__device__ __forceinline__ unsigned final32(const unsigned* L, int m, int rank, int lane)
{
    unsigned myv = (lane < m) ? L[lane] : 0xFFFFFFFFu;
    int c = 0;
    #pragma unroll
    for (int j = 0; j < 32; j++) {
        unsigned o = __shfl_sync(~0u, myv, j);
        c += (o < myv) || (o == myv && j < lane);
    }
    bool hit = (c == rank) && (lane < m);
    unsigned bal = __ballot_sync(~0u, hit);
    int src = __ffs(bal) - 1;
    return __shfl_sync(~0u, myv, src);
}

__device__ __forceinline__ unsigned solve_list(unsigned* L, int m, int rank,
                                               unsigned tp, int sh0, int lane)
{
    int sh = sh0, m_ = m, r = rank; unsigned tp_ = tp;
    while (m_ > 32 && sh >= 0) {
        unsigned d = list_pass(L, m_, r, sh, lane);
        tp_ |= d << sh; sh -= 4;
    }
    return (m_ > 32) ? tp_ : final32(L, m_, r, lane);
}

// ---------------------------------------------------------------------------
// Kernel 1b: exact 819th-smallest of bias (one warp) -> g_t0 window center
// ---------------------------------------------------------------------------
__global__ void t0_kernel(const float* __restrict__ bias)
{
    __shared__ unsigned sk[NC];
    const int lane = threadIdx.x & 31;
    for (int i = lane; i < NC; i += 32) sk[i] = f2u(bias[i]);
    __syncwarp();
    // solve from the full list; digits accumulate to exact value if needed
    unsigned ans;
    {
        int m = NC, r = KSEL, sh = 28; unsigned tp = 0;
        while (m > 32 && sh >= 0) {
            unsigned d = list_pass(sk, m, r, sh, lane);
            tp |= d << sh; sh -= 4;
        }
        ans = (m > 32) ? tp : final32(sk, m, r, lane);
    }
    if (lane == 0) g_t0 = u2f(ans);
}

// ---------------------------------------------------------------------------
// Kernel 2: windowed select around g_t0 (shared across all positions).
// ---------------------------------------------------------------------------
#define SEL_SMEM (2048 * 4 + 4 * 2 * SEL_CAP * 4)

__global__ void __launch_bounds__(128) select_kernel(const float* __restrict__ bias)
{
    extern __shared__ float smem[];
    float* sbias = smem;                          // 2048 floats
    unsigned* slist = (unsigned*)(smem + 2048);   // 4 warps * 2 * SEL_CAP

    const int tid = threadIdx.x;
    const int wid = tid >> 5, lane = tid & 31;

    {
        const float4* bsrc = (const float4*)bias;
        float4* bdst = (float4*)sbias;
        #pragma unroll
        for (int i = 0; i < 4; i++) bdst[tid + 128 * i] = bsrc[tid + 128 * i];
    }
    __syncthreads();

    const int pos = blockIdx.x * 4 + wid;
    const float4* vsrc = (const float4*)(g_conv + (size_t)pos * NC);
    unsigned* l1 = slist + wid * 2 * SEL_CAP;
    unsigned* l2 = l1 + SEL_CAP;

    const float t0 = g_t0;
    const float wlo = t0 - WIN, whi = t0 + WIN;
    const unsigned lt = (1u << lane) - 1u;

    // ---- windowed sweep: local below-counts, ballot-compact window only ----
    int cb1 = 0, cb2 = 0;     // local: # keys < wlo
    int n1 = 0, n2 = 0;       // warp-uniform: # keys in [wlo, whi)
    {
        const float4* bs4 = (const float4*)sbias;
        #pragma unroll 1
        for (int half = 0; half < 2; half++) {
            float4 vv[8], bv[8];
            #pragma unroll
            for (int t = 0; t < 8; t++) {
                vv[t] = __ldg(vsrc + (half * 8 + t) * 32 + lane);
                bv[t] = bs4[(half * 8 + t) * 32 + lane];
            }
            #pragma unroll
            for (int t = 0; t < 8; t++) {
                #pragma unroll
                for (int e = 0; e < 4; e++) {
                    float v = (&vv[t].x)[e], bb = (&bv[t].x)[e];
                    float k1 = bb - v, k2 = bb + v;
                    bool below1 = k1 < wlo;
                    bool in1 = !below1 && (k1 < whi);
                    bool below2 = k2 < wlo;
                    bool in2 = !below2 && (k2 < whi);
                    cb1 += below1;
                    cb2 += below2;
                    unsigned bi1 = __ballot_sync(~0u, in1);
                    if (in1) { int ix = n1 + __popc(bi1 & lt); if (ix < SEL_CAP) l1[ix] = f2u(k1); }
                    n1 += __popc(bi1);
                    unsigned bi2 = __ballot_sync(~0u, in2);
                    if (in2) { int ix = n2 + __popc(bi2 & lt); if (ix < SEL_CAP) l2[ix] = f2u(k2); }
                    n2 += __popc(bi2);
                }
            }
        }
    }
    int tb1 = wsum(cb1), tb2 = wsum(cb2);
    int r1 = KSEL - tb1, r2 = KSEL - tb2;
    bool ok1 = (r1 >= 0) && (r1 < n1) && (n1 <= SEL_CAP);
    bool ok2 = (r2 >= 0) && (r2 < n2) && (n2 <= SEL_CAP);

    unsigned ansu1, ansu2;
    if (ok1 && ok2) {
        ansu1 = solve_list(l1, n1, r1, 0, 28, lane);
        ansu2 = solve_list(l2, n2, r2, 0, 28, lane);
    } else {
        // ---- exact general radix path (rare) ----
        int rank1 = KSEL, rank2 = KSEL;
        unsigned top1 = 0, top2 = 0, maskTop = 0;
        int m1 = NC, m2 = NC;
        int shift = 28;
        unsigned dig1, dig2;
        {
            int cnt = hist_sweep<false>(vsrc, sbias, 0, 0, 0, shift, lane);
            pick_bins(cnt, rank1, rank2, dig1, dig2, m1, m2, lane);
            top1 |= dig1 << shift; top2 |= dig2 << shift;
            maskTop |= 0xFu << shift; shift -= 4;
        }
        while ((m1 > SEL_CAP || m2 > SEL_CAP) && shift >= 0) {
            int cnt = hist_sweep<true>(vsrc, sbias, top1, top2, maskTop, shift, lane);
            pick_bins(cnt, rank1, rank2, dig1, dig2, m1, m2, lane);
            top1 |= dig1 << shift; top2 |= dig2 << shift;
            maskTop |= 0xFu << shift; shift -= 4;
        }
        bool en1 = (m1 <= SEL_CAP), en2 = (m2 <= SEL_CAP);
        compact_sweep(vsrc, sbias, top1, top2, maskTop, l1, l2, en1, en2, lane);
        ansu1 = en1 ? solve_list(l1, m1, rank1, top1, shift, lane) : top1;
        ansu2 = en2 ? solve_list(l2, m2, rank2, top2, shift, lane) : top2;
    }

    if (lane == 0) {
        g_t1[pos] = u2f(ansu1);
        g_t2[pos] = u2f(ansu2);
    }
}

// ---------------------------------------------------------------------------
// Kernel 3: masks + (avg_pool_ceil(5,3) o adaptive(6)) as separable 6x27 map A.
// ---------------------------------------------------------------------------
__global__ void __launch_bounds__(128) pool_kernel(const float* __restrict__ bias,
                                                   float* __restrict__ out)
{
    __shared__ float st1[NPOS9], st2[NPOS9];
    __shared__ float sA[6][28];

    const int b = blockIdx.y;
    const int c = blockIdx.x * 128 + threadIdx.x;

    for (int i = threadIdx.x; i < NPOS9; i += 128) {
        st1[i] = g_t1[b * NPOS9 + i];
        st2[i] = g_t2[b * NPOS9 + i];
    }
    if (threadIdx.x < 27) {
        int wcol = threadIdx.x;
        const int sidx[6] = {0, 1, 3, 4, 6, 7};
        #pragma unroll
        for (int i = 0; i < 6; i++) {
            float a = 0.0f;
            #pragma unroll
            for (int q = 0; q < 2; q++) {
                int p = sidx[i] + q;
                int st = 3 * p, en = (st + 5 < 27) ? st + 5 : 27;
                if (wcol >= st && wcol < en) a += 0.5f / (float)(en - st);
            }
            sA[i][wcol] = a;
        }
    }
    __syncthreads();

    const float bc = bias[c];
    const float* p = g_conv + (size_t)b * NPOS9 * NC + c;

    float acc1[36], acc2[36];
    #pragma unroll
    for (int k = 0; k < 36; k++) { acc1[k] = 0.0f; acc2[k] = 0.0f; }

    int idx = 0;
    for (int h = 0; h < 27; h++) {
        float r1[6], r2[6];
        #pragma unroll
        for (int j = 0; j < 6; j++) { r1[j] = 0.0f; r2[j] = 0.0f; }
        for (int wcol = 0; wcol < 27; wcol++, idx++) {
            float v = __ldg(p + (size_t)idx * NC);
            float m1 = (bc - v < st1[idx]) ? 1.0f : 0.0f;
            float m2 = (bc + v < st2[idx]) ? 1.0f : 0.0f;
            #pragma unroll
            for (int j = 0; j < 6; j++) {
                float a = sA[j][wcol];
                r1[j] += a * m1;
                r2[j] += a * m2;
            }
        }
        #pragma unroll
        for (int i = 0; i < 6; i++) {
            float ah = sA[i][h];
            #pragma unroll
            for (int j = 0; j < 6; j++) {
                acc1[i * 6 + j] += ah * r1[j];
                acc2[i * 6 + j] += ah * r2[j];
            }
        }
    }

    float* o1 = out + ((size_t)(b * NC + c)) * 36;
    float* o2 = o1 + (size_t)NB * NC * 36;
    #pragma unroll
    for (int k = 0; k < 36; k++) { o1[k] = acc1[k]; o2[k] = acc2[k]; }
}

// ---------------------------------------------------------------------------
extern "C" void kernel_launch(void* const* d_in, const int* in_sizes, int n_in,
                              void* d_out, int out_size)
{
    const float* x    = (const float*)d_in[0]; // [64,3,32,32]
    const float* w    = (const float*)d_in[1]; // [2048,3,6,6]
    const float* bias = (const float*)d_in[2]; // [2048]
    float* out = (float*)d_out;                // [2][64,2048,6,6]

    cudaFuncSetAttribute(conv_kernel, cudaFuncAttributeMaxDynamicSharedMemorySize, CONV_SMEM);
    cudaFuncSetAttribute(select_kernel, cudaFuncAttributeMaxDynamicSharedMemorySize, SEL_SMEM);

    conv_kernel<<<dim3(16, 64), 256, CONV_SMEM>>>(x, w);
    t0_kernel<<<1, 32>>>(bias);
    select_kernel<<<TOTPOS / 4, 128, SEL_SMEM>>>(bias);
    pool_kernel<<<dim3(16, 64), 128>>>(bias, out);
}

// round 11
// speedup vs baseline: 1.4276x; 1.0873x over previous
#include <cuda_runtime.h>
#include <cstdint>

#define NB 64
#define NC 2048
#define NPOS9 729          // 27*27
#define TOTPOS (NB*NPOS9)  // 46656
#define KSEL 819
#define SEL_CAP 512
#define WIN 0.28f

__device__ float g_conv[(size_t)NB * NPOS9 * NC];  // NHWC: [b][p][c]
__device__ float g_t1[TOTPOS];
__device__ float g_t2[TOTPOS];
__device__ float g_t0;

// ---------------------------------------------------------------------------
// Kernel 1: conv (VALID, stride 1) -> NHWC scratch.  fp32 via fma.rn.f32x2.
// ---------------------------------------------------------------------------
#define CONV_XS2_U64 3072
#define CONV_W_U64  (108 * 4 * 16)
#define CONV_SMEM ((CONV_XS2_U64 + CONV_W_U64) * 8)

__global__ void __launch_bounds__(256) conv_kernel(const float* __restrict__ x,
                                                   const float* __restrict__ w)
{
    extern __shared__ unsigned long long smem64[];
    float2* xs2 = (float2*)smem64;                       // 3072 pairs {x,x}
    float2* ws2 = (float2*)(smem64 + CONV_XS2_U64);      // 6912 weight pairs
    const unsigned long long* xsu = smem64;
    const unsigned long long* wsu = smem64 + CONV_XS2_U64;

    const int b = blockIdx.y;
    const int c0 = blockIdx.x * 128;
    const int tid = threadIdx.x;

    {
        const float* xsrc = x + (size_t)b * 3072;
        #pragma unroll
        for (int i = 0; i < 12; i++) {
            int idx = tid + 256 * i;
            float v = xsrc[idx];
            xs2[idx] = make_float2(v, v);
        }
    }
    for (int idx = tid; idx < CONV_W_U64; idx += 256) {
        int ct = idx & 15;
        int kq = idx >> 4;
        int k = kq >> 2, q = kq & 3;
        int ch = c0 + ct * 8 + 2 * q;
        float a = w[(size_t)ch * 108 + k];
        float bb = w[(size_t)(ch + 1) * 108 + k];
        ws2[idx] = make_float2(a, bb);
    }
    __syncthreads();

    const int ch_tid = tid & 15;
    const int pos_tid = tid >> 4;
    const int ch0 = ch_tid * 8;

    for (int chunk = 0; chunk < 6; chunk++) {
        const int p0 = chunk * 128 + pos_tid * 8;
        int pbase[8];
        #pragma unroll
        for (int pp = 0; pp < 8; pp++) {
            int p = p0 + pp; if (p > 728) p = 728;
            int y = p / 27;
            pbase[pp] = y * 32 + (p - y * 27);
        }
        unsigned long long acc0[8], acc1[8], acc2[8], acc3[8];
        #pragma unroll
        for (int pp = 0; pp < 8; pp++) { acc0[pp] = 0ull; acc1[pp] = 0ull; acc2[pp] = 0ull; acc3[pp] = 0ull; }

        #pragma unroll 1
        for (int c = 0; c < 3; c++) {
            #pragma unroll 1
            for (int i = 0; i < 6; i++) {
                const unsigned long long* xrow = xsu + c * 1024 + i * 32;
                const int kbase = (c * 36 + i * 6) * 4;
                #pragma unroll
                for (int j = 0; j < 6; j++) {
                    const unsigned long long* wk = wsu + (size_t)(kbase + j * 4) * 16 + ch_tid;
                    unsigned long long w0 = wk[0], w1 = wk[16], w2 = wk[32], w3 = wk[48];
                    #pragma unroll
                    for (int pp = 0; pp < 8; pp++) {
                        unsigned long long xx = xrow[pbase[pp] + j];
                        asm("fma.rn.f32x2 %0, %1, %2, %0;" : "+l"(acc0[pp]) : "l"(w0), "l"(xx));
                        asm("fma.rn.f32x2 %0, %1, %2, %0;" : "+l"(acc1[pp]) : "l"(w1), "l"(xx));
                        asm("fma.rn.f32x2 %0, %1, %2, %0;" : "+l"(acc2[pp]) : "l"(w2), "l"(xx));
                        asm("fma.rn.f32x2 %0, %1, %2, %0;" : "+l"(acc3[pp]) : "l"(w3), "l"(xx));
                    }
                }
            }
        }
        #pragma unroll
        for (int pp = 0; pp < 8; pp++) {
            int p = p0 + pp;
            if (p < 729) {
                float* dst = g_conv + ((size_t)(b * NPOS9 + p)) * NC + c0 + ch0;
                float a, bb, cc, dd, e, f, g, h;
                asm("mov.b64 {%0, %1}, %2;" : "=f"(a), "=f"(bb) : "l"(acc0[pp]));
                asm("mov.b64 {%0, %1}, %2;" : "=f"(cc), "=f"(dd) : "l"(acc1[pp]));
                asm("mov.b64 {%0, %1}, %2;" : "=f"(e), "=f"(f) : "l"(acc2[pp]));
                asm("mov.b64 {%0, %1}, %2;" : "=f"(g), "=f"(h) : "l"(acc3[pp]));
                ((float4*)dst)[0] = make_float4(a, bb, cc, dd);
                ((float4*)dst)[1] = make_float4(e, f, g, h);
            }
        }
    }
}

// ---------------------------------------------------------------------------
// select helpers
// ---------------------------------------------------------------------------
__device__ __forceinline__ unsigned f2u(float f) {
    int b = __float_as_int(f);
    return (unsigned)(b ^ ((b >> 31) | 0x80000000));
}
__device__ __forceinline__ float u2f(unsigned u) {
    unsigned b = (u & 0x80000000u) ? (u & 0x7fffffffu) : ~u;
    return __uint_as_float(b);
}
__device__ __forceinline__ int wsum(int v) {
    #pragma unroll
    for (int o = 16; o; o >>= 1) v += __shfl_xor_sync(~0u, v, o);
    return v;
}
__device__ __forceinline__ unsigned wminu(unsigned v) {
    #pragma unroll
    for (int o = 16; o; o >>= 1) v = min(v, (unsigned)__shfl_xor_sync(~0u, v, o));
    return v;
}
__device__ __forceinline__ unsigned wmaxu(unsigned v) {
    #pragma unroll
    for (int o = 16; o; o >>= 1) v = max(v, (unsigned)__shfl_xor_sync(~0u, v, o));
    return v;
}

template<bool MASKED>
__device__ __forceinline__ int hist_sweep(const float4* __restrict__ vsrc,
                                          const float* __restrict__ sbias,
                                          unsigned top1, unsigned top2,
                                          unsigned maskTop, int shift, int lane)
{
    const unsigned bin = lane & 15;
    const unsigned r0 = (bin & 1) ? ~0u : 0u;
    const unsigned r1 = (bin & 2) ? ~0u : 0u;
    const unsigned r2 = (bin & 4) ? ~0u : 0u;
    const unsigned r3 = (bin & 8) ? ~0u : 0u;
    const bool br2 = (lane >= 16);
    int cnt = 0;
    const float4* bs4 = (const float4*)sbias;
    for (int t = 0; t < 16; t++) {
        float4 v4 = __ldg(vsrc + t * 32 + lane);
        float4 b4 = bs4[t * 32 + lane];
        #pragma unroll
        for (int e = 0; e < 4; e++) {
            float v = (&v4.x)[e], bb = (&b4.x)[e];
            unsigned u1 = f2u(bb - v), u2 = f2u(bb + v);
            bool a1 = MASKED ? (((u1 ^ top1) & maskTop) == 0) : true;
            bool a2 = MASKED ? (((u2 ^ top2) & maskTop) == 0) : true;
            unsigned d1 = u1 >> shift, d2 = u2 >> shift;
            unsigned B10 = __ballot_sync(~0u, a1 && (d1 & 1));
            unsigned B11 = __ballot_sync(~0u, a1 && (d1 & 2));
            unsigned B12 = __ballot_sync(~0u, a1 && (d1 & 4));
            unsigned B13 = __ballot_sync(~0u, a1 && (d1 & 8));
            unsigned A1  = MASKED ? __ballot_sync(~0u, a1) : ~0u;
            unsigned B20 = __ballot_sync(~0u, a2 && (d2 & 1));
            unsigned B21 = __ballot_sync(~0u, a2 && (d2 & 2));
            unsigned B22 = __ballot_sync(~0u, a2 && (d2 & 4));
            unsigned B23 = __ballot_sync(~0u, a2 && (d2 & 8));
            unsigned A2  = MASKED ? __ballot_sync(~0u, a2) : ~0u;
            unsigned Bb0 = br2 ? B20 : B10;
            unsigned Bb1 = br2 ? B21 : B11;
            unsigned Bb2 = br2 ? B22 : B12;
            unsigned Bb3 = br2 ? B23 : B13;
            unsigned A   = br2 ? A2  : A1;
            unsigned mm = A & ~((Bb3 ^ r3) | (Bb2 ^ r2) | (Bb1 ^ r1) | (Bb0 ^ r0));
            cnt += __popc(mm);
        }
    }
    return cnt;
}

__device__ __forceinline__ void pick_bins(int cnt, int& rank1, int& rank2,
                                          unsigned& dig1, unsigned& dig2,
                                          int& m1, int& m2, int lane)
{
    int incl = cnt;
    #pragma unroll
    for (int o = 1; o < 16; o <<= 1) {
        int n = __shfl_up_sync(~0u, incl, o, 16);
        if ((lane & 15) >= o) incl += n;
    }
    int excl = incl - cnt;
    int rk = (lane < 16) ? rank1 : rank2;
    bool hit = (rk >= excl) && (rk < incl);
    unsigned bal = __ballot_sync(~0u, hit);
    int src1 = __ffs(bal & 0xFFFFu) - 1;
    int src2 = 31 - __clz(bal & 0xFFFF0000u);
    int nr = rk - excl;
    dig1 = (unsigned)(src1 & 15);
    dig2 = (unsigned)(src2 & 15);
    rank1 = __shfl_sync(~0u, nr, src1);
    rank2 = __shfl_sync(~0u, nr, src2);
    m1 = __shfl_sync(~0u, cnt, src1);
    m2 = __shfl_sync(~0u, cnt, src2);
}

__device__ __forceinline__ void compact_sweep(const float4* __restrict__ vsrc,
                                              const float* __restrict__ sbias,
                                              unsigned top1, unsigned top2,
                                              unsigned maskTop,
                                              unsigned* l1, unsigned* l2,
                                              bool en1, bool en2, int lane)
{
    int n1 = 0, n2 = 0;
    const unsigned lt = (1u << lane) - 1u;
    const float4* bs4 = (const float4*)sbias;
    for (int t = 0; t < 16; t++) {
        float4 v4 = __ldg(vsrc + t * 32 + lane);
        float4 b4 = bs4[t * 32 + lane];
        #pragma unroll
        for (int e = 0; e < 4; e++) {
            float v = (&v4.x)[e], bb = (&b4.x)[e];
            unsigned u1 = f2u(bb - v), u2 = f2u(bb + v);
            bool k1 = en1 && (((u1 ^ top1) & maskTop) == 0);
            bool k2 = en2 && (((u2 ^ top2) & maskTop) == 0);
            unsigned bal1 = __ballot_sync(~0u, k1);
            if (k1) l1[n1 + __popc(bal1 & lt)] = u1;
            n1 += __popc(bal1);
            unsigned bal2 = __ballot_sync(~0u, k2);
            if (k2) l2[n2 + __popc(bal2 & lt)] = u2;
            n2 += __popc(bal2);
        }
    }
}

__device__ __forceinline__ unsigned list_pass(unsigned* L, int& m, int& rank,
                                              int shift, int lane)
{
    const unsigned bin = lane & 15;
    const unsigned r0 = (bin & 1) ? ~0u : 0u;
    const unsigned r1 = (bin & 2) ? ~0u : 0u;
    const unsigned r2 = (bin & 4) ? ~0u : 0u;
    const unsigned r3 = (bin & 8) ? ~0u : 0u;
    const unsigned lt = (1u << lane) - 1u;
    int iters = (m + 31) >> 5;
    int cnt = 0;
    for (int i = 0; i < iters; i++) {
        int idx = i * 32 + lane;
        bool act = idx < m;
        unsigned u = act ? L[idx] : 0u;
        unsigned d = u >> shift;
        unsigned B0 = __ballot_sync(~0u, act && (d & 1));
        unsigned B1 = __ballot_sync(~0u, act && (d & 2));
        unsigned B2 = __ballot_sync(~0u, act && (d & 4));
        unsigned B3 = __ballot_sync(~0u, act && (d & 8));
        unsigned A  = __ballot_sync(~0u, act);
        unsigned mm = A & ~((B3 ^ r3) | (B2 ^ r2) | (B1 ^ r1) | (B0 ^ r0));
        cnt += __popc(mm);
    }
    int incl = cnt;
    #pragma unroll
    for (int o = 1; o < 16; o <<= 1) {
        int n = __shfl_up_sync(~0u, incl, o, 16);
        if ((lane & 15) >= o) incl += n;
    }
    int excl = incl - cnt;
    bool hit = (lane < 16) && (rank >= excl) && (rank < incl);
    unsigned bal = __ballot_sync(~0u, hit);
    int src = __ffs(bal) - 1;
    unsigned dig = (unsigned)src;
    int nr = rank - excl;
    rank = __shfl_sync(~0u, nr, src);
    int w = 0;
    for (int i = 0; i < iters; i++) {
        int idx = i * 32 + lane;
        bool act = idx < m;
        unsigned u = act ? L[idx] : 0u;
        bool keep = act && (((u >> shift) & 15u) == dig);
        unsigned kb = __ballot_sync(~0u, keep);
        if (keep) L[w + __popc(kb & lt)] = u;
        w += __popc(kb);
    }
    m = w;
    return dig;
}

__device__ __forceinline__ unsigned final32(const unsigned* L, int m, int rank, int lane)
{
    unsigned myv = (lane < m) ? L[lane] : 0xFFFFFFFFu;
    int c = 0;
    #pragma unroll
    for (int j = 0; j < 32; j++) {
        unsigned o = __shfl_sync(~0u, myv, j);
        c += (o < myv) || (o == myv && j < lane);
    }
    bool hit = (c == rank) && (lane < m);
    unsigned bal = __ballot_sync(~0u, hit);
    int src = __ffs(bal) - 1;
    return __shfl_sync(~0u, myv, src);
}

__device__ __forceinline__ unsigned solve_list(unsigned* L, int m, int rank,
                                               unsigned tp, int sh0, int lane)
{
    int sh = sh0, m_ = m, r = rank; unsigned tp_ = tp;
    while (m_ > 32 && sh >= 0) {
        unsigned d = list_pass(L, m_, r, sh, lane);
        tp_ |= d << sh; sh -= 4;
    }
    return (m_ > 32) ? tp_ : final32(L, m_, r, lane);
}

// start radix at the first nibble where umin/umax differ
__device__ __forceinline__ unsigned solve_list_smart(unsigned* L, int m, int rank,
                                                     unsigned umin, unsigned umax, int lane)
{
    if (umin == umax) return umin;
    int bit = 31 - __clz(umin ^ umax);
    int sh0 = (bit >> 2) << 2;
    unsigned pref = (sh0 >= 28) ? 0u : (umin & (~0u << (sh0 + 4)));
    return solve_list(L, m, rank, pref, sh0, lane);
}

// ---------------------------------------------------------------------------
// Kernel 1b: exact 819th-smallest of bias (one warp) -> g_t0 window center
// ---------------------------------------------------------------------------
__global__ void t0_kernel(const float* __restrict__ bias)
{
    __shared__ unsigned sk[NC];
    const int lane = threadIdx.x & 31;
    for (int i = lane; i < NC; i += 32) sk[i] = f2u(bias[i]);
    __syncwarp();
    unsigned ans;
    {
        int m = NC, r = KSEL, sh = 28; unsigned tp = 0;
        while (m > 32 && sh >= 0) {
            unsigned d = list_pass(sk, m, r, sh, lane);
            tp |= d << sh; sh -= 4;
        }
        ans = (m > 32) ? tp : final32(sk, m, r, lane);
    }
    if (lane == 0) g_t0 = u2f(ans);
}

// ---------------------------------------------------------------------------
// Kernel 2: windowed select around g_t0 (shared across all positions).
// ---------------------------------------------------------------------------
#define SEL_SMEM (2048 * 4 + 4 * 2 * SEL_CAP * 4)

__global__ void __launch_bounds__(128) select_kernel(const float* __restrict__ bias)
{
    extern __shared__ float smem[];
    float* sbias = smem;                          // 2048 floats
    unsigned* slist = (unsigned*)(smem + 2048);   // 4 warps * 2 * SEL_CAP

    const int tid = threadIdx.x;
    const int wid = tid >> 5, lane = tid & 31;

    {
        const float4* bsrc = (const float4*)bias;
        float4* bdst = (float4*)sbias;
        #pragma unroll
        for (int i = 0; i < 4; i++) bdst[tid + 128 * i] = bsrc[tid + 128 * i];
    }
    __syncthreads();

    const int pos = blockIdx.x * 4 + wid;
    const float4* vsrc = (const float4*)(g_conv + (size_t)pos * NC);
    unsigned* l1 = slist + wid * 2 * SEL_CAP;
    unsigned* l2 = l1 + SEL_CAP;

    const float t0 = g_t0;
    const float wlo = t0 - WIN, whi = t0 + WIN;
    const unsigned lt = (1u << lane) - 1u;

    // ---- windowed sweep: local below-counts, ballot-compact window only ----
    int cb1 = 0, cb2 = 0;     // local: # keys < wlo
    int n1 = 0, n2 = 0;       // warp-uniform: # keys in [wlo, whi)
    unsigned mn1 = 0xFFFFFFFFu, mx1 = 0u, mn2 = 0xFFFFFFFFu, mx2 = 0u;
    {
        const float4* bs4 = (const float4*)sbias;
        #pragma unroll 1
        for (int half = 0; half < 2; half++) {
            float4 vv[8], bv[8];
            #pragma unroll
            for (int t = 0; t < 8; t++) {
                vv[t] = __ldg(vsrc + (half * 8 + t) * 32 + lane);
                bv[t] = bs4[(half * 8 + t) * 32 + lane];
            }
            #pragma unroll
            for (int t = 0; t < 8; t++) {
                #pragma unroll
                for (int e = 0; e < 4; e++) {
                    float v = (&vv[t].x)[e], bb = (&bv[t].x)[e];
                    float k1 = bb - v, k2 = bb + v;
                    bool below1 = k1 < wlo;
                    bool in1 = !below1 && (k1 < whi);
                    bool below2 = k2 < wlo;
                    bool in2 = !below2 && (k2 < whi);
                    cb1 += below1;
                    cb2 += below2;
                    unsigned bi1 = __ballot_sync(~0u, in1);
                    if (in1) {
                        unsigned u1 = f2u(k1);
                        mn1 = min(mn1, u1); mx1 = max(mx1, u1);
                        int ix = n1 + __popc(bi1 & lt); if (ix < SEL_CAP) l1[ix] = u1;
                    }
                    n1 += __popc(bi1);
                    unsigned bi2 = __ballot_sync(~0u, in2);
                    if (in2) {
                        unsigned u2 = f2u(k2);
                        mn2 = min(mn2, u2); mx2 = max(mx2, u2);
                        int ix = n2 + __popc(bi2 & lt); if (ix < SEL_CAP) l2[ix] = u2;
                    }
                    n2 += __popc(bi2);
                }
            }
        }
    }
    int tb1 = wsum(cb1), tb2 = wsum(cb2);
    int r1 = KSEL - tb1, r2 = KSEL - tb2;
    bool ok1 = (r1 >= 0) && (r1 < n1) && (n1 <= SEL_CAP);
    bool ok2 = (r2 >= 0) && (r2 < n2) && (n2 <= SEL_CAP);

    unsigned ansu1, ansu2;
    if (ok1 && ok2) {
        mn1 = wminu(mn1); mx1 = wmaxu(mx1);
        mn2 = wminu(mn2); mx2 = wmaxu(mx2);
        ansu1 = solve_list_smart(l1, n1, r1, mn1, mx1, lane);
        ansu2 = solve_list_smart(l2, n2, r2, mn2, mx2, lane);
    } else {
        // ---- exact general radix path (rare) ----
        int rank1 = KSEL, rank2 = KSEL;
        unsigned top1 = 0, top2 = 0, maskTop = 0;
        int m1 = NC, m2 = NC;
        int shift = 28;
        unsigned dig1, dig2;
        {
            int cnt = hist_sweep<false>(vsrc, sbias, 0, 0, 0, shift, lane);
            pick_bins(cnt, rank1, rank2, dig1, dig2, m1, m2, lane);
            top1 |= dig1 << shift; top2 |= dig2 << shift;
            maskTop |= 0xFu << shift; shift -= 4;
        }
        while ((m1 > SEL_CAP || m2 > SEL_CAP) && shift >= 0) {
            int cnt = hist_sweep<true>(vsrc, sbias, top1, top2, maskTop, shift, lane);
            pick_bins(cnt, rank1, rank2, dig1, dig2, m1, m2, lane);
            top1 |= dig1 << shift; top2 |= dig2 << shift;
            maskTop |= 0xFu << shift; shift -= 4;
        }
        bool en1 = (m1 <= SEL_CAP), en2 = (m2 <= SEL_CAP);
        compact_sweep(vsrc, sbias, top1, top2, maskTop, l1, l2, en1, en2, lane);
        ansu1 = en1 ? solve_list(l1, m1, rank1, top1, shift, lane) : top1;
        ansu2 = en2 ? solve_list(l2, m2, rank2, top2, shift, lane) : top2;
    }

    if (lane == 0) {
        g_t1[pos] = u2f(ansu1);
        g_t2[pos] = u2f(ansu2);
    }
}

// ---------------------------------------------------------------------------
// Kernel 3: masks + pooling with smem row staging (MLP=7 coalesced bursts).
// ---------------------------------------------------------------------------
__global__ void __launch_bounds__(128) pool_kernel(const float* __restrict__ bias,
                                                   float* __restrict__ out)
{
    __shared__ float st1[NPOS9], st2[NPOS9];
    __shared__ float sA[6][28];
    __shared__ float4 s4[27 * 32];     // one h-row: 27 positions x 128 ch (16B aligned)
    float* srow = (float*)s4;

    const int b = blockIdx.y;
    const int c0 = blockIdx.x * 128;
    const int tid = threadIdx.x;
    const int c = c0 + tid;

    for (int i = tid; i < NPOS9; i += 128) {
        st1[i] = g_t1[b * NPOS9 + i];
        st2[i] = g_t2[b * NPOS9 + i];
    }
    if (tid < 27) {
        int wcol = tid;
        const int sidx[6] = {0, 1, 3, 4, 6, 7};
        #pragma unroll
        for (int i = 0; i < 6; i++) {
            float a = 0.0f;
            #pragma unroll
            for (int q = 0; q < 2; q++) {
                int p = sidx[i] + q;
                int st = 3 * p, en = (st + 5 < 27) ? st + 5 : 27;
                if (wcol >= st && wcol < en) a += 0.5f / (float)(en - st);
            }
            sA[i][wcol] = a;
        }
    }
    __syncthreads();

    const float bc = bias[c];

    float acc1[36], acc2[36];
    #pragma unroll
    for (int k = 0; k < 36; k++) { acc1[k] = 0.0f; acc2[k] = 0.0f; }

    #pragma unroll 1
    for (int h = 0; h < 27; h++) {
        // stage row h: 27 positions x 128 ch = 864 float4, coalesced, MLP=7
        const float* rowbase = g_conv + ((size_t)(b * NPOS9 + h * 27)) * NC + c0;
        #pragma unroll
        for (int k = 0; k < 7; k++) {
            int j = tid + 128 * k;
            if (j < 864) {
                int p = j >> 5, cq = j & 31;
                s4[j] = __ldg((const float4*)(rowbase + (size_t)p * NC) + cq);
            }
        }
        __syncthreads();

        float r1[6], r2[6];
        #pragma unroll
        for (int j = 0; j < 6; j++) { r1[j] = 0.0f; r2[j] = 0.0f; }
        const int hbase = h * 27;
        #pragma unroll 9
        for (int wcol = 0; wcol < 27; wcol++) {
            float v = srow[wcol * 128 + tid];
            float m1 = (bc - v < st1[hbase + wcol]) ? 1.0f : 0.0f;
            float m2 = (bc + v < st2[hbase + wcol]) ? 1.0f : 0.0f;
            #pragma unroll
            for (int j = 0; j < 6; j++) {
                float a = sA[j][wcol];
                r1[j] += a * m1;
                r2[j] += a * m2;
            }
        }
        #pragma unroll
        for (int i = 0; i < 6; i++) {
            float ah = sA[i][h];
            #pragma unroll
            for (int j = 0; j < 6; j++) {
                acc1[i * 6 + j] += ah * r1[j];
                acc2[i * 6 + j] += ah * r2[j];
            }
        }
        __syncthreads();
    }

    float* o1 = out + ((size_t)(b * NC + c)) * 36;
    float* o2 = o1 + (size_t)NB * NC * 36;
    #pragma unroll
    for (int k = 0; k < 36; k++) { o1[k] = acc1[k]; o2[k] = acc2[k]; }
}

// ---------------------------------------------------------------------------
extern "C" void kernel_launch(void* const* d_in, const int* in_sizes, int n_in,
                              void* d_out, int out_size)
{
    const float* x    = (const float*)d_in[0]; // [64,3,32,32]
    const float* w    = (const float*)d_in[1]; // [2048,3,6,6]
    const float* bias = (const float*)d_in[2]; // [2048]
    float* out = (float*)d_out;                // [2][64,2048,6,6]

    cudaFuncSetAttribute(conv_kernel, cudaFuncAttributeMaxDynamicSharedMemorySize, CONV_SMEM);
    cudaFuncSetAttribute(select_kernel, cudaFuncAttributeMaxDynamicSharedMemorySize, SEL_SMEM);

    conv_kernel<<<dim3(16, 64), 256, CONV_SMEM>>>(x, w);
    t0_kernel<<<1, 32>>>(bias);
    select_kernel<<<TOTPOS / 4, 128, SEL_SMEM>>>(bias);
    pool_kernel<<<dim3(16, 64), 128>>>(bias, out);
}